// round 9
// baseline (speedup 1.0000x reference)
#include <cuda_runtime.h>

#define B_ 32
#define M_ 2048
#define H_ 1024
#define NTOK (B_*M_)
#define THRESH 0.99f
#define BLOCKS_PER_BATCH (M_/4)   // main: 4 tokens per block

// Scratch (no allocations allowed).
__device__ int g_rank[NTOK];          // clip(cumsum(run)-1, 0, M-1)
__device__ unsigned char g_runb[NTOK];// decoded run mask
__device__ int g_src[NTOK];           // run_new ? rank : -1
__device__ int g_gidx[NTOK];          // packed row d -> source row in h, -1 => zero row
__device__ int g_done[B_];            // per-batch completion counters (reset each call)

// ---------------------------------------------------------------------------
// K0: wire-format probe + decode + per-batch rank scan. Both format
// interpretations are loaded BEFORE the probe resolves.
// ---------------------------------------------------------------------------
__global__ void rank_kernel(const void* __restrict__ run) {
    const int b = blockIdx.x;
    const int t = threadIdx.x;            // 256 threads
    const unsigned int* w = (const unsigned int*)run;

    if (t == 0) g_done[b] = 0;

    // issue everything up front: probe words + u8 view + i32 view
    unsigned int p0 = w[b * 512 + t];
    unsigned int p1 = w[b * 512 + 256 + t];
    const int base = t * 8;
    uint2 u8v = *(const uint2*)((const unsigned char*)run + b * M_ + base);
    int4 i0 = ((const int4*)((const int*)run + b * M_ + base))[0];
    int4 i1 = ((const int4*)((const int*)run + b * M_ + base))[1];

    int found = ((p0 | p1) & 0xFFFFFF00u) ? 1 : 0;
    const int fmt_u8 = __syncthreads_or(found);

    int v[8];
    if (fmt_u8) {
        v[0] = (u8v.x & 0x000000FFu) != 0; v[1] = (u8v.x & 0x0000FF00u) != 0;
        v[2] = (u8v.x & 0x00FF0000u) != 0; v[3] = (u8v.x & 0xFF000000u) != 0;
        v[4] = (u8v.y & 0x000000FFu) != 0; v[5] = (u8v.y & 0x0000FF00u) != 0;
        v[6] = (u8v.y & 0x00FF0000u) != 0; v[7] = (u8v.y & 0xFF000000u) != 0;
    } else {
        v[0] = i0.x != 0; v[1] = i0.y != 0; v[2] = i0.z != 0; v[3] = i0.w != 0;
        v[4] = i1.x != 0; v[5] = i1.y != 0; v[6] = i1.z != 0; v[7] = i1.w != 0;
    }
    int s = 0;
    #pragma unroll
    for (int i = 0; i < 8; i++) {
        s += v[i];
        g_runb[b * M_ + base + i] = (unsigned char)v[i];
    }

    const int lane = t & 31, warp = t >> 5;
    int x = s;  // inclusive warp scan of per-thread sums
    #pragma unroll
    for (int o = 1; o < 32; o <<= 1) {
        int y = __shfl_up_sync(0xffffffffu, x, o);
        if (lane >= o) x += y;
    }
    __shared__ int wsum[8], woff[8];
    if (lane == 31) wsum[warp] = x;
    __syncthreads();
    if (t == 0) { int a = 0; for (int i = 0; i < 8; i++) { woff[i] = a; a += wsum[i]; } }
    __syncthreads();

    int c = woff[warp] + (x - s);
    #pragma unroll
    for (int i = 0; i < 8; i++) {
        c += v[i];
        int rk = c - 1;
        if (rk < 0) rk = 0;
        g_rank[b * M_ + base + i] = rk;
    }
}

// ---------------------------------------------------------------------------
// K1: warp-per-token (4 warps / 128 threads). PDL: before the dependency
// wait, each block issues ALL rank-independent memory traffic — W -> smem,
// its wh row (8x float4 into registers), and accp — so wave-1 saturates DRAM
// with required reads while rank_kernel finishes. Only the h[rank] load and
// g_runb/g_rank reads sit behind cudaGridDependencySynchronize().
// Tail: last block per batch compacts g_src -> g_gidx.
// ---------------------------------------------------------------------------
__global__ __launch_bounds__(128) void main_kernel(
    const float* __restrict__ h, const float* __restrict__ W,
    const float* __restrict__ bias, const float* __restrict__ wh,
    const float* __restrict__ accp,
    float* __restrict__ weighted_out, float* __restrict__ acc_out)
{
    __shared__ float sW[H_];

    const int warp = threadIdx.x >> 5, lane = threadIdx.x & 31;
    const int tok = blockIdx.x * 4 + warp;
    const int b = tok >> 11;               // uniform per block (4 | 2048)

    // ---- rank-independent prefetch (overlaps rank_kernel via PDL) ----
    for (int i = threadIdx.x; i < H_ / 4; i += 128)
        ((float4*)sW)[i] = ((const float4*)W)[i];

    const float4* whrow = (const float4*)(wh + (size_t)tok * H_);
    float4 wv4[8];
    #pragma unroll
    for (int i = 0; i < 8; i++) wv4[i] = whrow[lane + i * 32];
    float acc = accp[tok];
    const float bv = bias[0];

    cudaGridDependencySynchronize();   // rank_kernel outputs now visible
    __syncthreads();

    const bool running = g_runb[tok] != 0;
    const int rank = g_rank[tok];

    float4 hv[8];
    float dot = 0.0f;
    if (running) {
        const float4* hrow = (const float4*)(h + ((size_t)b * M_ + rank) * H_);
        #pragma unroll
        for (int i = 0; i < 8; i++) {
            float4 a = hrow[lane + i * 32];
            hv[i] = a;
            float4 wv = ((const float4*)sW)[lane + i * 32];
            dot += a.x * wv.x;
            dot += a.y * wv.y;
            dot += a.z * wv.z;
            dot += a.w * wv.w;
        }
    } else {
        #pragma unroll
        for (int i = 0; i < 8; i++) hv[i] = make_float4(0.f, 0.f, 0.f, 0.f);
    }
    #pragma unroll
    for (int o = 16; o > 0; o >>= 1)
        dot += __shfl_xor_sync(0xffffffffu, dot, o);

    float p_adj = 0.0f;
    bool run_new = false;
    if (running) {
        float z = dot + bv;
        float p = 1.0f / (1.0f + expf(-z));
        float acc_new = acc + p;
        run_new = acc_new < THRESH;
        p_adj = run_new ? p : (1.0f - (acc_new - p));
        acc = acc_new;
    }
    if (lane == 0) {
        acc_out[tok] = acc;
        g_src[tok] = run_new ? rank : -1;
    }

    float4* wo = (float4*)(weighted_out + (size_t)tok * H_);
    const float q = 1.0f - p_adj;
    #pragma unroll
    for (int i = 0; i < 8; i++) {
        float4 o4;
        o4.x = hv[i].x * p_adj + wv4[i].x * q;
        o4.y = hv[i].y * p_adj + wv4[i].y * q;
        o4.z = hv[i].z * p_adj + wv4[i].z * q;
        o4.w = hv[i].w * p_adj + wv4[i].w * q;
        wo[lane + i * 32] = o4;
    }

    // ---- fused per-batch compaction: last-arriving block does the scan ----
    __shared__ int s_last;
    __syncthreads();                 // all warps' g_src writes issued
    if (threadIdx.x == 0) {
        __threadfence();             // release g_src to other SMs
        int n = atomicAdd(&g_done[b], 1);
        s_last = (n == BLOCKS_PER_BATCH - 1);
    }
    __syncthreads();
    if (!s_last) return;

    const int t = threadIdx.x;
    const int base = b * M_ + t * 16;
    int src[16], v[16];
    int s = 0;
    #pragma unroll
    for (int i = 0; i < 16; i++) {
        src[i] = g_src[base + i];
        v[i] = (src[i] >= 0) ? 1 : 0;
        s += v[i];
        g_gidx[base + i] = -1;       // default: zero row
    }
    int x = s;
    #pragma unroll
    for (int o = 1; o < 32; o <<= 1) {
        int y = __shfl_up_sync(0xffffffffu, x, o);
        if (lane >= o) x += y;
    }
    __shared__ int cw[4], co[4];
    if (lane == 31) cw[warp] = x;
    __syncthreads();
    if (t == 0) { int a = 0; for (int i = 0; i < 4; i++) { co[i] = a; a += cw[i]; } }
    __syncthreads();                 // also orders the -1 init before scatter

    int pos = co[warp] + (x - s);
    #pragma unroll
    for (int i = 0; i < 16; i++) {
        if (v[i]) {
            g_gidx[b * M_ + pos] = src[i];
            pos++;
        }
    }
}

// ---------------------------------------------------------------------------
// K3: packed[b,d,:] = gidx>=0 ? h[b,gidx,:] : 0. Warp-per-row gather,
// batched loads. PDL hides the launch gap behind main's tail.
// ---------------------------------------------------------------------------
__global__ __launch_bounds__(128) void pack_kernel(const float* __restrict__ h,
                                                   float* __restrict__ packed)
{
    cudaGridDependencySynchronize();   // main_kernel writes (g_gidx) visible

    const int warp = threadIdx.x >> 5, lane = threadIdx.x & 31;
    const int tok = blockIdx.x * 4 + warp;
    const int b = tok >> 11;
    const int g = g_gidx[tok];

    float4* out = (float4*)(packed + (size_t)tok * H_);
    if (g >= 0) {
        const float4* hrow = (const float4*)(h + ((size_t)b * M_ + g) * H_);
        float4 r[8];
        #pragma unroll
        for (int i = 0; i < 8; i++) r[i] = hrow[lane + i * 32];
        #pragma unroll
        for (int i = 0; i < 8; i++) out[lane + i * 32] = r[i];
    } else {
        const float4 z = make_float4(0.f, 0.f, 0.f, 0.f);
        #pragma unroll
        for (int i = 0; i < 8; i++) out[lane + i * 32] = z;
    }
}

// ---------------------------------------------------------------------------
extern "C" void kernel_launch(void* const* d_in, const int* in_sizes, int n_in,
                              void* d_out, int out_size) {
    const float* h    = (const float*)d_in[0];
    const float* W    = (const float*)d_in[1];
    const float* bias = (const float*)d_in[2];
    const float* wh   = (const float*)d_in[3];
    const float* accp = (const float*)d_in[4];
    const void*  run  = d_in[5];

    float* out      = (float*)d_out;
    float* packed   = out;                              // [B,M,H]
    float* weighted = out + (size_t)NTOK * H_;          // [B,M,H]
    float* acc      = out + 2 * (size_t)NTOK * H_;      // [B,M,1]

    rank_kernel<<<B_, 256>>>(run);

    cudaLaunchAttribute attr[1];
    attr[0].id = cudaLaunchAttributeProgrammaticStreamSerialization;
    attr[0].val.programmaticStreamSerializationAllowed = 1;

    {   // main: wh/W/accp prefetch overlaps rank via PDL
        cudaLaunchConfig_t cfg = {};
        cfg.gridDim = dim3(NTOK / 4);
        cfg.blockDim = dim3(128);
        cfg.dynamicSmemBytes = 0;
        cfg.stream = 0;
        cfg.attrs = attr;
        cfg.numAttrs = 1;
        cudaLaunchKernelEx(&cfg, main_kernel, h, W, bias, wh, accp,
                           weighted, acc);
    }
    {   // pack: launch gap hidden behind main's tail
        cudaLaunchConfig_t cfg = {};
        cfg.gridDim = dim3(NTOK / 4);
        cfg.blockDim = dim3(128);
        cfg.dynamicSmemBytes = 0;
        cfg.stream = 0;
        cfg.attrs = attr;
        cfg.numAttrs = 1;
        cudaLaunchKernelEx(&cfg, pack_kernel, h, packed);
    }
}

// round 10
// speedup vs baseline: 1.0544x; 1.0544x over previous
#include <cuda_runtime.h>

#define B_ 32
#define M_ 2048
#define H_ 1024
#define NTOK (B_*M_)
#define THRESH 0.99f
#define BLOCKS_PER_BATCH (M_/4)   // main: 4 tokens per block

// Scratch (no allocations allowed).
__device__ int g_rank[NTOK];          // clip(cumsum(run)-1, 0, M-1)
__device__ unsigned char g_runb[NTOK];// decoded run mask
__device__ int g_src[NTOK];           // run_new ? rank : -1
__device__ int g_gidx[NTOK];          // packed row d -> source row in h, -1 => zero row
__device__ int g_done[B_];            // per-batch completion counters (reset each call)

// ---------------------------------------------------------------------------
// K0: wire-format probe + decode + per-batch rank scan. Both format
// interpretations are loaded BEFORE the probe resolves.
// ---------------------------------------------------------------------------
__global__ void rank_kernel(const void* __restrict__ run) {
    const int b = blockIdx.x;
    const int t = threadIdx.x;            // 256 threads
    const unsigned int* w = (const unsigned int*)run;

    if (t == 0) g_done[b] = 0;

    // issue everything up front: probe words + u8 view + i32 view
    unsigned int p0 = w[b * 512 + t];
    unsigned int p1 = w[b * 512 + 256 + t];
    const int base = t * 8;
    uint2 u8v = *(const uint2*)((const unsigned char*)run + b * M_ + base);
    int4 i0 = ((const int4*)((const int*)run + b * M_ + base))[0];
    int4 i1 = ((const int4*)((const int*)run + b * M_ + base))[1];

    int found = ((p0 | p1) & 0xFFFFFF00u) ? 1 : 0;
    const int fmt_u8 = __syncthreads_or(found);

    int v[8];
    if (fmt_u8) {
        v[0] = (u8v.x & 0x000000FFu) != 0; v[1] = (u8v.x & 0x0000FF00u) != 0;
        v[2] = (u8v.x & 0x00FF0000u) != 0; v[3] = (u8v.x & 0xFF000000u) != 0;
        v[4] = (u8v.y & 0x000000FFu) != 0; v[5] = (u8v.y & 0x0000FF00u) != 0;
        v[6] = (u8v.y & 0x00FF0000u) != 0; v[7] = (u8v.y & 0xFF000000u) != 0;
    } else {
        v[0] = i0.x != 0; v[1] = i0.y != 0; v[2] = i0.z != 0; v[3] = i0.w != 0;
        v[4] = i1.x != 0; v[5] = i1.y != 0; v[6] = i1.z != 0; v[7] = i1.w != 0;
    }
    int s = 0;
    #pragma unroll
    for (int i = 0; i < 8; i++) {
        s += v[i];
        g_runb[b * M_ + base + i] = (unsigned char)v[i];
    }

    const int lane = t & 31, warp = t >> 5;
    int x = s;  // inclusive warp scan of per-thread sums
    #pragma unroll
    for (int o = 1; o < 32; o <<= 1) {
        int y = __shfl_up_sync(0xffffffffu, x, o);
        if (lane >= o) x += y;
    }
    __shared__ int wsum[8], woff[8];
    if (lane == 31) wsum[warp] = x;
    __syncthreads();
    if (t == 0) { int a = 0; for (int i = 0; i < 8; i++) { woff[i] = a; a += wsum[i]; } }
    __syncthreads();

    int c = woff[warp] + (x - s);
    #pragma unroll
    for (int i = 0; i < 8; i++) {
        c += v[i];
        int rk = c - 1;
        if (rk < 0) rk = 0;
        g_rank[b * M_ + base + i] = rk;
    }
}

// ---------------------------------------------------------------------------
// K1: warp-per-token (4 warps / 128 threads). PDL overlap, occupancy-neutral:
// before the dependency wait each block stages its rank-independent traffic
// into SMEM (W 4KB + its 4 wh rows 16KB) so wave-1 keeps DRAM busy while
// rank_kernel finishes — without raising live register count across the hot
// loop (the R9 register-prefetch mistake). Tail: per-batch fused compaction.
// ---------------------------------------------------------------------------
__global__ __launch_bounds__(128) void main_kernel(
    const float* __restrict__ h, const float* __restrict__ W,
    const float* __restrict__ bias, const float* __restrict__ wh,
    const float* __restrict__ accp,
    float* __restrict__ weighted_out, float* __restrict__ acc_out)
{
    __shared__ float sW[H_];
    __shared__ float sWH[4 * H_];      // 4 token rows of weighted_h

    const int warp = threadIdx.x >> 5, lane = threadIdx.x & 31;
    const int tok = blockIdx.x * 4 + warp;
    const int b = tok >> 11;               // uniform per block (4 | 2048)

    // ---- rank-independent prefetch (overlaps rank_kernel via PDL) ----
    for (int i = threadIdx.x; i < H_ / 4; i += 128)
        ((float4*)sW)[i] = ((const float4*)W)[i];

    {   // each warp stages its own token's wh row: 8x LDG.128 -> 8x STS.128
        const float4* whrow = (const float4*)(wh + (size_t)tok * H_);
        float4* swh = (float4*)(sWH + warp * H_);
        float4 r[8];
        #pragma unroll
        for (int i = 0; i < 8; i++) r[i] = whrow[lane + i * 32];
        #pragma unroll
        for (int i = 0; i < 8; i++) swh[lane + i * 32] = r[i];
    }
    float acc = accp[tok];
    const float bv = bias[0];

    cudaGridDependencySynchronize();   // rank_kernel outputs now visible
    __syncthreads();

    const bool running = g_runb[tok] != 0;
    const int rank = g_rank[tok];

    float4 hv[8];
    float dot = 0.0f;
    if (running) {
        const float4* hrow = (const float4*)(h + ((size_t)b * M_ + rank) * H_);
        #pragma unroll
        for (int i = 0; i < 8; i++) {
            float4 a = hrow[lane + i * 32];
            hv[i] = a;
            float4 wv = ((const float4*)sW)[lane + i * 32];
            dot += a.x * wv.x;
            dot += a.y * wv.y;
            dot += a.z * wv.z;
            dot += a.w * wv.w;
        }
    } else {
        #pragma unroll
        for (int i = 0; i < 8; i++) hv[i] = make_float4(0.f, 0.f, 0.f, 0.f);
    }
    #pragma unroll
    for (int o = 16; o > 0; o >>= 1)
        dot += __shfl_xor_sync(0xffffffffu, dot, o);

    float p_adj = 0.0f;
    bool run_new = false;
    if (running) {
        float z = dot + bv;
        float p = 1.0f / (1.0f + expf(-z));
        float acc_new = acc + p;
        run_new = acc_new < THRESH;
        p_adj = run_new ? p : (1.0f - (acc_new - p));
        acc = acc_new;
    }
    if (lane == 0) {
        acc_out[tok] = acc;
        g_src[tok] = run_new ? rank : -1;
    }

    float4* wo = (float4*)(weighted_out + (size_t)tok * H_);
    const float4* swh = (const float4*)(sWH + warp * H_);
    const float q = 1.0f - p_adj;
    #pragma unroll
    for (int i = 0; i < 8; i++) {
        float4 w4 = swh[lane + i * 32];
        float4 o4;
        o4.x = hv[i].x * p_adj + w4.x * q;
        o4.y = hv[i].y * p_adj + w4.y * q;
        o4.z = hv[i].z * p_adj + w4.z * q;
        o4.w = hv[i].w * p_adj + w4.w * q;
        wo[lane + i * 32] = o4;
    }

    // ---- fused per-batch compaction: last-arriving block does the scan ----
    __shared__ int s_last;
    __syncthreads();                 // all warps' g_src writes issued
    if (threadIdx.x == 0) {
        __threadfence();             // release g_src to other SMs
        int n = atomicAdd(&g_done[b], 1);
        s_last = (n == BLOCKS_PER_BATCH - 1);
    }
    __syncthreads();
    if (!s_last) return;

    const int t = threadIdx.x;
    const int base = b * M_ + t * 16;
    int src[16], v[16];
    int s = 0;
    #pragma unroll
    for (int i = 0; i < 16; i++) {
        src[i] = g_src[base + i];
        v[i] = (src[i] >= 0) ? 1 : 0;
        s += v[i];
        g_gidx[base + i] = -1;       // default: zero row
    }
    int x = s;
    #pragma unroll
    for (int o = 1; o < 32; o <<= 1) {
        int y = __shfl_up_sync(0xffffffffu, x, o);
        if (lane >= o) x += y;
    }
    __shared__ int cw[4], co[4];
    if (lane == 31) cw[warp] = x;
    __syncthreads();
    if (t == 0) { int a = 0; for (int i = 0; i < 4; i++) { co[i] = a; a += cw[i]; } }
    __syncthreads();                 // also orders the -1 init before scatter

    int pos = co[warp] + (x - s);
    #pragma unroll
    for (int i = 0; i < 16; i++) {
        if (v[i]) {
            g_gidx[b * M_ + pos] = src[i];
            pos++;
        }
    }
}

// ---------------------------------------------------------------------------
// K3: packed[b,d,:] = gidx>=0 ? h[b,gidx,:] : 0. Warp-per-row gather,
// batched loads. PDL hides the launch gap behind main's tail.
// ---------------------------------------------------------------------------
__global__ __launch_bounds__(128) void pack_kernel(const float* __restrict__ h,
                                                   float* __restrict__ packed)
{
    cudaGridDependencySynchronize();   // main_kernel writes (g_gidx) visible

    const int warp = threadIdx.x >> 5, lane = threadIdx.x & 31;
    const int tok = blockIdx.x * 4 + warp;
    const int b = tok >> 11;
    const int g = g_gidx[tok];

    float4* out = (float4*)(packed + (size_t)tok * H_);
    if (g >= 0) {
        const float4* hrow = (const float4*)(h + ((size_t)b * M_ + g) * H_);
        float4 r[8];
        #pragma unroll
        for (int i = 0; i < 8; i++) r[i] = hrow[lane + i * 32];
        #pragma unroll
        for (int i = 0; i < 8; i++) out[lane + i * 32] = r[i];
    } else {
        const float4 z = make_float4(0.f, 0.f, 0.f, 0.f);
        #pragma unroll
        for (int i = 0; i < 8; i++) out[lane + i * 32] = z;
    }
}

// ---------------------------------------------------------------------------
extern "C" void kernel_launch(void* const* d_in, const int* in_sizes, int n_in,
                              void* d_out, int out_size) {
    const float* h    = (const float*)d_in[0];
    const float* W    = (const float*)d_in[1];
    const float* bias = (const float*)d_in[2];
    const float* wh   = (const float*)d_in[3];
    const float* accp = (const float*)d_in[4];
    const void*  run  = d_in[5];

    float* out      = (float*)d_out;
    float* packed   = out;                              // [B,M,H]
    float* weighted = out + (size_t)NTOK * H_;          // [B,M,H]
    float* acc      = out + 2 * (size_t)NTOK * H_;      // [B,M,1]

    rank_kernel<<<B_, 256>>>(run);

    cudaLaunchAttribute attr[1];
    attr[0].id = cudaLaunchAttributeProgrammaticStreamSerialization;
    attr[0].val.programmaticStreamSerializationAllowed = 1;

    {   // main: W/wh/accp prefetch (smem) overlaps rank via PDL
        cudaLaunchConfig_t cfg = {};
        cfg.gridDim = dim3(NTOK / 4);
        cfg.blockDim = dim3(128);
        cfg.dynamicSmemBytes = 0;
        cfg.stream = 0;
        cfg.attrs = attr;
        cfg.numAttrs = 1;
        cudaLaunchKernelEx(&cfg, main_kernel, h, W, bias, wh, accp,
                           weighted, acc);
    }
    {   // pack: launch gap hidden behind main's tail
        cudaLaunchConfig_t cfg = {};
        cfg.gridDim = dim3(NTOK / 4);
        cfg.blockDim = dim3(128);
        cfg.dynamicSmemBytes = 0;
        cfg.stream = 0;
        cfg.attrs = attr;
        cfg.numAttrs = 1;
        cudaLaunchKernelEx(&cfg, pack_kernel, h, packed);
    }
}